// round 12
// baseline (speedup 1.0000x reference)
#include <cuda_runtime.h>
#include <cuda_fp16.h>
#include <math.h>
#include <stdint.h>

#define T_TOK 8192
#define H_DIM 1024
#define E_NUM 8
#define F_DIM 2048
#define TM 128
#define MAX_ROWS (2*T_TOK + E_NUM*TM)   /* 17408 */
#define MAX_TILES (MAX_ROWS/TM)         /* 136   */

#define KC    64            /* k-elements per chunk */
#define PITCH 144           /* 128B data + 16B pad (9 segs, coprime w/ 8) */
#define PART  18432         /* 128 rows * 144B */
#define STG   (2*PART)      /* A | B = 36864 */
#define NSTG  3
#define SMEM_SROWS (NSTG*STG)          /* 110592 */
#define SMEM_AOFF  (SMEM_SROWS + 512)
#define SMEM_TOTAL (SMEM_AOFF + 512)   /* 111616 -> 2 CTAs/SM */

#define W1_ITEMS (16 * MAX_TILES)      /* 2176 gemm1 tiles */
#define W2_ITEMS (8 * MAX_TILES)       /* 1088 gemm2 tiles */
#define W_TOTAL  (W1_ITEMS + W2_ITEMS)
#define GRID_PERSIST 296               /* 2 CTAs/SM * 148 SMs */

/* ================= PTX helpers (family-common: sm_80+ only) ================= */
__device__ __forceinline__ uint32_t smem_u32(const void* p) {
    uint32_t a;
    asm("{ .reg .u64 t; cvta.to.shared.u64 t, %1; cvt.u32.u64 %0, t; }" : "=r"(a) : "l"(p));
    return a;
}
#define CP_ASYNC16(saddr, gptr) \
    asm volatile("cp.async.cg.shared.global [%0], [%1], 16;" :: "r"(saddr), "l"(gptr))
#define CP_COMMIT() asm volatile("cp.async.commit_group;" ::: "memory")
#define CP_WAIT1()  asm volatile("cp.async.wait_group 1;" ::: "memory")

__device__ __forceinline__ void ldsm_x4(uint32_t* r, uint32_t addr) {
    asm volatile("ldmatrix.sync.aligned.m8n8.x4.shared.b16 {%0,%1,%2,%3}, [%4];"
        : "=r"(r[0]), "=r"(r[1]), "=r"(r[2]), "=r"(r[3]) : "r"(addr));
}
__device__ __forceinline__ void mma16816(float* d, const uint32_t* a, const uint32_t* b) {
    asm volatile("mma.sync.aligned.m16n8k16.row.col.f32.f16.f16.f32 "
        "{%0,%1,%2,%3}, {%4,%5,%6,%7}, {%8,%9}, {%0,%1,%2,%3};"
        : "+f"(d[0]), "+f"(d[1]), "+f"(d[2]), "+f"(d[3])
        : "r"(a[0]), "r"(a[1]), "r"(a[2]), "r"(a[3]), "r"(b[0]), "r"(b[1]));
}

/* ================= scratch (device globals) ================= */
__device__ __half g_xh[(size_t)T_TOK * H_DIM];
__device__ __half g_w1[(size_t)E_NUM * F_DIM * H_DIM];   /* [e][n=F][k=H] */
__device__ __half g_w2[(size_t)E_NUM * H_DIM * F_DIM];   /* [e][n=H][k=F] */
__device__ __half g_h[(size_t)MAX_ROWS * F_DIM];         /* pad rows stay 0 */
__device__ float g_eout[(size_t)MAX_ROWS * H_DIM];
__device__ int   g_rowmap[MAX_ROWS];
__device__ float g_rowprob[MAX_ROWS];
__device__ int   g_tokrow[T_TOK * 2];
__device__ int   g_counts[E_NUM];
__device__ int   g_tile_expert[MAX_TILES];
__device__ int   g_e01[T_TOK*2];
__device__ float g_p01[T_TOK*2];
__device__ int   g_block_done;
__device__ int   g_work;
__device__ int   g_ready[MAX_TILES];

/* ========== launch 1: tiny bookkeeping init ================================ */
__global__ void init_kernel() {
    int i = blockIdx.x * blockDim.x + threadIdx.x;
    if (i < MAX_ROWS) g_rowmap[i] = -1;
    if (i < MAX_TILES) g_ready[i] = 0;
    if (i < E_NUM) g_counts[i] = 0;
    if (i == 0) { g_block_done = 0; g_work = 0; }
}

/* ========== launch 2: weight transpose conversions ========================= */
__device__ __forceinline__ void conv_w_body(const float* __restrict__ w,
                                            __half* __restrict__ dst,
                                            int K, int N, int e) {
    __shared__ float t[32][33];
    int n0 = blockIdx.x * 32;
    int k0 = blockIdx.y * 32;
    if (n0 >= N || k0 >= K) return;
    int tx = threadIdx.x & 31, ty = threadIdx.x >> 5;
    const float* src = w + (size_t)e * K * N;
#pragma unroll
    for (int r = 0; r < 4; r++)
        t[ty + r*8][tx] = src[(size_t)(k0 + ty + r*8) * N + n0 + tx];
    __syncthreads();
#pragma unroll
    for (int r = 0; r < 4; r++) {
        int n = n0 + ty + r*8;
        dst[((size_t)e * N + n) * K + k0 + tx] = __float2half_rn(t[tx][ty + r*8]);
    }
}
__global__ void conv_w_all(const float* __restrict__ w1, const float* __restrict__ w2) {
    int z = blockIdx.z;
    if (z < E_NUM) conv_w_body(w1, g_w1, H_DIM, F_DIM, z);
    else           conv_w_body(w2, g_w2, F_DIM, H_DIM, z - E_NUM);
}

/* ========== launch 3: router (+x->fp16) + last-block scan + placement ====== */
__global__ void router_kernel(const float* __restrict__ x,
                              const float* __restrict__ rw,
                              const float* __restrict__ rb) {
    __shared__ int s_cnt[E_NUM][256];
    __shared__ int s_excl[E_NUM][256];
    __shared__ int s_offs[E_NUM];
    __shared__ int s_flag;

    int tid  = threadIdx.x;
    int gw   = (blockIdx.x * blockDim.x + tid) >> 5;
    int lane = tid & 31;
    const float* xp = x + (size_t)gw * H_DIM;
    __half* xhp = g_xh + (size_t)gw * H_DIM;
    float acc[E_NUM];
#pragma unroll
    for (int e = 0; e < E_NUM; e++) acc[e] = 0.f;
    for (int k = lane; k < H_DIM; k += 32) {
        float xv = xp[k];
        xhp[k] = __float2half_rn(xv);                 /* fused x conversion */
        const float4* w = (const float4*)(rw + (size_t)k * E_NUM);
        float4 w0 = w[0], w1v = w[1];
        acc[0] += xv * w0.x;  acc[1] += xv * w0.y;
        acc[2] += xv * w0.z;  acc[3] += xv * w0.w;
        acc[4] += xv * w1v.x; acc[5] += xv * w1v.y;
        acc[6] += xv * w1v.z; acc[7] += xv * w1v.w;
    }
#pragma unroll
    for (int off = 16; off; off >>= 1)
#pragma unroll
        for (int e = 0; e < E_NUM; e++)
            acc[e] += __shfl_xor_sync(0xffffffffu, acc[e], off);
    if (lane == 0) {
#pragma unroll
        for (int e = 0; e < E_NUM; e++) acc[e] += rb[e];
        int i0 = 0;
#pragma unroll
        for (int e = 1; e < E_NUM; e++) if (acc[e] > acc[i0]) i0 = e;
        int i1 = (i0 == 0) ? 1 : 0;
#pragma unroll
        for (int e = 0; e < E_NUM; e++)
            if (e != i0 && acc[e] > acc[i1]) i1 = e;
        float ex = expf(acc[i1] - acc[i0]);
        g_e01[2*gw] = i0;  g_e01[2*gw+1] = i1;
        g_p01[2*gw] = 1.f / (1.f + ex);
        g_p01[2*gw+1] = ex / (1.f + ex);
        atomicAdd(&g_counts[i0], 1);
        atomicAdd(&g_counts[i1], 1);
    }

    __threadfence();
    __syncthreads();
    if (tid == 0)
        s_flag = (atomicAdd(&g_block_done, 1) == (int)gridDim.x - 1);
    __syncthreads();
    if (!s_flag) return;
    __threadfence();

    if (tid == 0) {
        int off = 0;
        for (int e = 0; e < E_NUM; e++) {
            s_offs[e] = off;
            int nt = (g_counts[e] + TM - 1) / TM;
            for (int i = 0; i < nt; i++) g_tile_expert[off / TM + i] = e;
            off += nt * TM;
        }
        for (int i = off / TM; i < MAX_TILES; i++) g_tile_expert[i] = -1;
    }
    __syncthreads();

    int lc[E_NUM];
#pragma unroll
    for (int e = 0; e < E_NUM; e++) lc[e] = 0;
    for (int j = 0; j < 32; j++) {
        int t = j * 256 + tid;
        int e0 = g_e01[2*t], e1 = g_e01[2*t+1];
#pragma unroll
        for (int e = 0; e < E_NUM; e++) lc[e] += (e == e0) + (e == e1);
    }
#pragma unroll
    for (int e = 0; e < E_NUM; e++) s_cnt[e][tid] = lc[e];
    __syncthreads();

    {
        int wid = tid >> 5;
        int carry = 0;
        for (int seg = 0; seg < 8; seg++) {
            int v = s_cnt[wid][seg * 32 + lane];
            int inc = v;
#pragma unroll
            for (int o = 1; o < 32; o <<= 1) {
                int n = __shfl_up_sync(0xffffffffu, inc, o);
                if (lane >= o) inc += n;
            }
            s_excl[wid][seg * 32 + lane] = carry + inc - v;
            carry += __shfl_sync(0xffffffffu, inc, 31);
        }
    }
    __syncthreads();

#pragma unroll
    for (int e = 0; e < E_NUM; e++) lc[e] = 0;
    for (int j = 0; j < 32; j++) {
        int t = j * 256 + tid;
#pragma unroll
        for (int s = 0; s < 2; s++) {
            int e = g_e01[2*t + s];
            int pos = 0;
#pragma unroll
            for (int e2 = 0; e2 < E_NUM; e2++)
                if (e2 == e) { pos = lc[e2]; lc[e2]++; }
            int r = s_offs[e] + s_excl[e][tid] + pos;
            g_rowmap[r]  = t;
            g_rowprob[r] = g_p01[2*t + s];
            g_tokrow[2*t + s] = r;
        }
    }
}

/* ================= mma.sync GEMM core (128x128, KC=64, 3-stage) ============ */

__device__ __forceinline__ void load_stage(
    int c, int s, int nch, int tid,
    const __half* __restrict__ A, const __half* __restrict__ B,
    const unsigned* __restrict__ aoff, int col0, int K, uint32_t sb)
{
    if (c < nch) {
        uint32_t sbase = sb + (uint32_t)s * STG;
#pragma unroll
        for (int t = 0; t < 4; t++) {               /* A: 128 rows x 128B */
            int idx = tid + t * 256;
            int r = idx >> 3, seg = idx & 7;
            unsigned off = aoff[r] + (unsigned)c * KC + seg * 8;
            CP_ASYNC16(sbase + (uint32_t)r * PITCH + seg * 16, A + off);
        }
#pragma unroll
        for (int t = 0; t < 4; t++) {               /* B: 128 n-rows x 128B */
            int idx = tid + t * 256;
            int r = idx >> 3, seg = idx & 7;
            size_t off = (size_t)(col0 + r) * K + c * KC + seg * 8;
            CP_ASYNC16(sbase + PART + (uint32_t)r * PITCH + seg * 16, B + off);
        }
    }
    CP_COMMIT();
}

__device__ __forceinline__ void compute_stage(
    float acc[2][8][4], uint32_t sbase, int lane, int mbase, int nbase)
{
#pragma unroll
    for (int ks = 0; ks < 4; ks++) {
        uint32_t a[2][4], b[16];
        uint32_t arow = sbase + (uint32_t)(mbase + (lane & 15)) * PITCH
                        + ks * 32 + (lane >> 4) * 16;
#pragma unroll
        for (int mt = 0; mt < 2; mt++)
            ldsm_x4(a[mt], arow + mt * 16 * PITCH);
        uint32_t brow = sbase + PART
                        + (uint32_t)(nbase + ((lane >> 4) & 1) * 8 + (lane & 7)) * PITCH
                        + ks * 32 + ((lane >> 3) & 1) * 16;
#pragma unroll
        for (int p = 0; p < 4; p++)
            ldsm_x4(&b[p * 4], brow + p * 16 * PITCH);
#pragma unroll
        for (int mt = 0; mt < 2; mt++)
#pragma unroll
            for (int nt = 0; nt < 8; nt++)
                mma16816(acc[mt][nt], a[mt], &b[(nt >> 1) * 4 + (nt & 1) * 2]);
    }
}

__device__ __forceinline__ void gemm_mainloop(
    float acc[2][8][4],
    const __half* __restrict__ A, const __half* __restrict__ B,
    const unsigned* __restrict__ aoff, int col0, int K, int nch,
    uint32_t sb, int tid, int lane, int mbase, int nbase)
{
    load_stage(0, 0, nch, tid, A, B, aoff, col0, K, sb);
    load_stage(1, 1, nch, tid, A, B, aoff, col0, K, sb);
    int s = 0, sl = 2;
    for (int c = 0; c < nch; c++) {
        CP_WAIT1();
        __syncthreads();
        load_stage(c + 2, sl, nch, tid, A, B, aoff, col0, K, sb);
        compute_stage(acc, sb + (uint32_t)s * STG, lane, mbase, nbase);
        if (++s == NSTG) s = 0;
        if (++sl == NSTG) sl = 0;
    }
    __syncthreads();   /* all warps done with smem before epilogue reuses it */
}

__device__ __forceinline__ void stage_acc(float acc[2][8][4], float* sacc,
                                          int lane, int mbase, int nbase) {
    int groupID = lane >> 2, tig = lane & 3;
#pragma unroll
    for (int mt = 0; mt < 2; mt++)
#pragma unroll
        for (int nt = 0; nt < 8; nt++) {
            int r = mbase + mt * 16 + groupID;
            int cc = nbase + nt * 8 + tig * 2;
            sacc[r * 132 + cc]           = acc[mt][nt][0];
            sacc[r * 132 + cc + 1]       = acc[mt][nt][1];
            sacc[(r + 8) * 132 + cc]     = acc[mt][nt][2];
            sacc[(r + 8) * 132 + cc + 1] = acc[mt][nt][3];
        }
}

/* ------------- launch 4 (ncu target): persistent fused GEMM1 -> GEMM2 ------ */
__global__ __launch_bounds__(256, 2)
void gemm_fused(const float* __restrict__ b1, const float* __restrict__ b2) {
    extern __shared__ char smem[];
    uint32_t sb = smem_u32(smem);
    int tid = threadIdx.x, wid = tid >> 5, lane = tid & 31;
    int mbase = (wid >> 1) * 32, nbase = (wid & 1) * 64;
    int* srows = (int*)(smem + SMEM_SROWS);
    unsigned* aoff = (unsigned*)(smem + SMEM_AOFF);
    __shared__ int s_w;

    for (;;) {
        if (tid == 0) s_w = atomicAdd(&g_work, 1);
        __syncthreads();                 /* also fences prev iter's sacc reads */
        int w = s_w;
        if (w >= W_TOTAL) return;

        if (w < W1_ITEMS) {
            /* ======== GEMM1 tile: col x = w&15, row-tile y = w>>4 ======== */
            int y = w >> 4, xcol = w & 15;
            int e = g_tile_expert[y];
            if (e >= 0) {
                int row0 = y * TM, col0 = xcol * TM;
                if (tid < TM) {
                    int rm = g_rowmap[row0 + tid];
                    srows[tid] = rm;
                    aoff[tid] = (unsigned)((rm < 0 ? 0 : rm) * H_DIM);
                }
                __syncthreads();

                float acc[2][8][4];
#pragma unroll
                for (int i = 0; i < 2; i++)
#pragma unroll
                    for (int j = 0; j < 8; j++)
#pragma unroll
                        for (int q = 0; q < 4; q++) acc[i][j][q] = 0.f;

                gemm_mainloop(acc, g_xh, g_w1 + (size_t)e * F_DIM * H_DIM,
                              aoff, col0, H_DIM, H_DIM / KC, sb, tid, lane, mbase, nbase);

                float* sacc = (float*)smem;
                stage_acc(acc, sacc, lane, mbase, nbase);
                __syncthreads();

                int row = tid >> 1, hc = (tid & 1) * 64;
                if (srows[row] >= 0) {
                    const float* bp = b1 + (size_t)e * F_DIM + col0 + hc;
                    __half* dh = g_h + (size_t)(row0 + row) * F_DIM + col0 + hc;
                    const float* sp = sacc + row * 132 + hc;
                    unsigned u[32];
#pragma unroll
                    for (int j = 0; j < 32; j++) {
                        float v0 = sp[2*j]   + bp[2*j];
                        float v1 = sp[2*j+1] + bp[2*j+1];
                        v0 = v0 > 0.f ? v0 : 0.f;
                        v1 = v1 > 0.f ? v1 : 0.f;
                        __half2 h2 = __floats2half2_rn(v0, v1);
                        u[j] = *(unsigned*)&h2;
                    }
#pragma unroll
                    for (int q = 0; q < 8; q++)
                        *(uint4*)(dh + q * 8) = make_uint4(u[4*q], u[4*q+1], u[4*q+2], u[4*q+3]);
                }
            }
            /* signal: this column-tile of row-tile y is complete */
            __threadfence();
            __syncthreads();
            if (tid == 0) atomicAdd(&g_ready[y], 1);
        } else {
            /* ======== GEMM2 tile: col x = w2&7, row-tile y = w2>>3 ======== */
            int w2 = w - W1_ITEMS;
            int y = w2 >> 3, xcol = w2 & 7;
            int e = g_tile_expert[y];
            if (e < 0) continue;
            /* wait for all 16 gemm1 column-tiles of row-tile y */
            if (tid == 0) {
                volatile int* rp = g_ready + y;
                while (*rp < 16) { }
            }
            __syncthreads();
            __threadfence();

            int row0 = y * TM, col0 = xcol * TM;
            if (tid < TM) {
                srows[tid] = g_rowmap[row0 + tid];
                aoff[tid] = (unsigned)((row0 + tid) * F_DIM);
            }
            __syncthreads();

            float acc[2][8][4];
#pragma unroll
            for (int i = 0; i < 2; i++)
#pragma unroll
                for (int j = 0; j < 8; j++)
#pragma unroll
                    for (int q = 0; q < 4; q++) acc[i][j][q] = 0.f;

            gemm_mainloop(acc, g_h, g_w2 + (size_t)e * H_DIM * F_DIM,
                          aoff, col0, F_DIM, F_DIM / KC, sb, tid, lane, mbase, nbase);

            float* sacc = (float*)smem;
            stage_acc(acc, sacc, lane, mbase, nbase);
            __syncthreads();

            int row = tid >> 1, hc = (tid & 1) * 64;
            int rm = srows[row];
            if (rm >= 0) {
                float p = g_rowprob[row0 + row];
                const float* bp = b2 + (size_t)e * H_DIM + col0 + hc;
                float* op = g_eout + (size_t)(row0 + row) * H_DIM + col0 + hc;
                const float* sp = sacc + row * 132 + hc;
#pragma unroll
                for (int q = 0; q < 16; q++) {
                    float4 v;
                    v.x = p * (sp[4*q]   + bp[4*q]);
                    v.y = p * (sp[4*q+1] + bp[4*q+1]);
                    v.z = p * (sp[4*q+2] + bp[4*q+2]);
                    v.w = p * (sp[4*q+3] + bp[4*q+3]);
                    *(float4*)(op + 4*q) = v;
                }
            }
        }
    }
}

/* ------------- launch 5: combine two expert rows per token ----------------- */
__global__ void combine_kernel(float* __restrict__ out) {
    int i = blockIdx.x * blockDim.x + threadIdx.x;
    int t = i >> 8, j = i & 255;
    int r0 = g_tokrow[2*t], r1 = g_tokrow[2*t+1];
    float4 a = *((const float4*)g_eout + (size_t)r0 * 256 + j);
    float4 b = *((const float4*)g_eout + (size_t)r1 * 256 + j);
    float4 v; v.x = a.x + b.x; v.y = a.y + b.y; v.z = a.z + b.z; v.w = a.w + b.w;
    *((float4*)out + (size_t)t * 256 + j) = v;
}

/* ================= launch ================= */
extern "C" void kernel_launch(void* const* d_in, const int* in_sizes, int n_in,
                              void* d_out, int out_size) {
    const float* x  = (const float*)d_in[0];
    const float* rw = (const float*)d_in[1];
    const float* rb = (const float*)d_in[2];
    const float* w1 = (const float*)d_in[3];
    const float* b1 = (const float*)d_in[4];
    const float* w2 = (const float*)d_in[5];
    const float* b2 = (const float*)d_in[6];
    float* out = (float*)d_out;

    cudaFuncSetAttribute(gemm_fused, cudaFuncAttributeMaxDynamicSharedMemorySize, SMEM_TOTAL);

    /* 1 */ init_kernel<<<(MAX_ROWS + 255) / 256, 256>>>();
    /* 2 */ conv_w_all<<<dim3(64, 64, 2 * E_NUM), 256>>>(w1, w2);
    /* 3 */ router_kernel<<<T_TOK * 32 / 256, 256>>>(x, rw, rb);
    /* 4 */ gemm_fused<<<GRID_PERSIST, 256, SMEM_TOTAL>>>(b1, b2);  /* ncu lands here */
    /* 5 */ combine_kernel<<<T_TOK * (H_DIM/4) / 256, 256>>>(out);
}

// round 13
// speedup vs baseline: 1.0369x; 1.0369x over previous
#include <cuda_runtime.h>
#include <cuda_fp16.h>
#include <math.h>
#include <stdint.h>

#define T_TOK 8192
#define H_DIM 1024
#define E_NUM 8
#define F_DIM 2048
#define TM 128
#define MAX_ROWS (2*T_TOK + E_NUM*TM)   /* 17408 */
#define MAX_TILES (MAX_ROWS/TM)         /* 136   */

#define KC    64            /* k-elements per chunk */
#define PITCH 144           /* 128B data + 16B pad (9 segs, coprime w/ 8) */
#define PART  18432         /* 128 rows * 144B */
#define STG   (2*PART)      /* A | B = 36864 */
#define NSTG  3
#define SMEM_SROWS (NSTG*STG)          /* 110592 */
#define SMEM_AOFF  (SMEM_SROWS + 512)
#define SMEM_TOTAL (SMEM_AOFF + 512)   /* 111616 -> 2 CTAs/SM */

/* ================= PTX helpers (family-common: sm_80+ only) ================= */
__device__ __forceinline__ uint32_t smem_u32(const void* p) {
    uint32_t a;
    asm("{ .reg .u64 t; cvta.to.shared.u64 t, %1; cvt.u32.u64 %0, t; }" : "=r"(a) : "l"(p));
    return a;
}
#define CP_ASYNC16(saddr, gptr) \
    asm volatile("cp.async.cg.shared.global [%0], [%1], 16;" :: "r"(saddr), "l"(gptr))
#define CP_COMMIT() asm volatile("cp.async.commit_group;" ::: "memory")
#define CP_WAIT1()  asm volatile("cp.async.wait_group 1;" ::: "memory")

__device__ __forceinline__ void ldsm_x4(uint32_t* r, uint32_t addr) {
    asm volatile("ldmatrix.sync.aligned.m8n8.x4.shared.b16 {%0,%1,%2,%3}, [%4];"
        : "=r"(r[0]), "=r"(r[1]), "=r"(r[2]), "=r"(r[3]) : "r"(addr));
}
__device__ __forceinline__ void mma16816(float* d, const uint32_t* a, const uint32_t* b) {
    asm volatile("mma.sync.aligned.m16n8k16.row.col.f32.f16.f16.f32 "
        "{%0,%1,%2,%3}, {%4,%5,%6,%7}, {%8,%9}, {%0,%1,%2,%3};"
        : "+f"(d[0]), "+f"(d[1]), "+f"(d[2]), "+f"(d[3])
        : "r"(a[0]), "r"(a[1]), "r"(a[2]), "r"(a[3]), "r"(b[0]), "r"(b[1]));
}

/* ================= scratch (device globals) ================= */
__device__ __half g_xh[(size_t)T_TOK * H_DIM];
__device__ __half g_w1[(size_t)E_NUM * F_DIM * H_DIM];   /* [e][n=F][k=H] */
__device__ __half g_w2[(size_t)E_NUM * H_DIM * F_DIM];   /* [e][n=H][k=F] */
__device__ __half g_h[(size_t)MAX_ROWS * F_DIM];         /* pad rows stay 0 */
__device__ float g_eout[(size_t)MAX_ROWS * H_DIM];
__device__ int   g_rowmap[MAX_ROWS];
__device__ float g_rowprob[MAX_ROWS];
__device__ int   g_tokrow[T_TOK * 2];
__device__ int   g_counts[E_NUM];
__device__ int   g_tile_expert[MAX_TILES];
__device__ int   g_e01[T_TOK*2];
__device__ float g_p01[T_TOK*2];
__device__ int   g_block_done;

/* ========== launch 1: tiny bookkeeping init ================================ */
__global__ void init_kernel() {
    int i = blockIdx.x * blockDim.x + threadIdx.x;
    if (i < MAX_ROWS) g_rowmap[i] = -1;
    if (i < E_NUM) g_counts[i] = 0;
    if (i == 0) g_block_done = 0;
}

/* ========== launch 2: weight transpose conversions (vectorized) ============ */
__device__ __forceinline__ void conv_w_body(const float* __restrict__ w,
                                            __half* __restrict__ dst,
                                            int K, int N, int e) {
    __shared__ float t[32][33];
    int n0 = blockIdx.x * 32;
    int k0 = blockIdx.y * 32;
    if (n0 >= N || k0 >= K) return;   /* block-uniform */
    int tid = threadIdx.x;            /* 128 threads */
    const float* src = w + (size_t)e * K * N;

    /* load 32x32 fp32 tile: float4 reads, 2 passes of 16 rows */
    {
        int k = tid >> 3, n4 = (tid & 7) * 4;     /* rows 0..15 */
#pragma unroll
        for (int p = 0; p < 2; p++) {
            float4 v = *(const float4*)(src + (size_t)(k0 + k + p*16) * N + n0 + n4);
            t[k + p*16][n4]   = v.x;  t[k + p*16][n4+1] = v.y;
            t[k + p*16][n4+2] = v.z;  t[k + p*16][n4+3] = v.w;
        }
    }
    __syncthreads();

    /* store transposed: each thread converts 8 k-values of one n-row -> uint4 */
    {
        int n = tid & 31, kseg = (tid >> 5) * 8;  /* 4 segs x 8 k */
        unsigned u[4];
#pragma unroll
        for (int q = 0; q < 4; q++) {
            __half2 h2 = __floats2half2_rn(t[kseg + 2*q][n], t[kseg + 2*q + 1][n]);
            u[q] = *(unsigned*)&h2;
        }
        *(uint4*)(dst + ((size_t)e * N + n0 + n) * K + k0 + kseg) =
            make_uint4(u[0], u[1], u[2], u[3]);
    }
}
__global__ void conv_w_all(const float* __restrict__ w1, const float* __restrict__ w2) {
    int z = blockIdx.z;
    if (z < E_NUM) conv_w_body(w1, g_w1, H_DIM, F_DIM, z);
    else           conv_w_body(w2, g_w2, F_DIM, H_DIM, z - E_NUM);
}

/* ========== launch 3: router (+x->fp16) + last-block scan + placement ====== */
__global__ void router_kernel(const float* __restrict__ x,
                              const float* __restrict__ rw,
                              const float* __restrict__ rb) {
    __shared__ int s_cnt[E_NUM][256];
    __shared__ int s_excl[E_NUM][256];
    __shared__ int s_offs[E_NUM];
    __shared__ int s_flag;

    int tid  = threadIdx.x;
    int gw   = (blockIdx.x * blockDim.x + tid) >> 5;
    int lane = tid & 31;
    const float* xp = x + (size_t)gw * H_DIM;
    __half* xhp = g_xh + (size_t)gw * H_DIM;
    float acc[E_NUM];
#pragma unroll
    for (int e = 0; e < E_NUM; e++) acc[e] = 0.f;
    for (int k = lane; k < H_DIM; k += 32) {
        float xv = xp[k];
        xhp[k] = __float2half_rn(xv);                 /* fused x conversion */
        const float4* w = (const float4*)(rw + (size_t)k * E_NUM);
        float4 w0 = w[0], w1v = w[1];
        acc[0] += xv * w0.x;  acc[1] += xv * w0.y;
        acc[2] += xv * w0.z;  acc[3] += xv * w0.w;
        acc[4] += xv * w1v.x; acc[5] += xv * w1v.y;
        acc[6] += xv * w1v.z; acc[7] += xv * w1v.w;
    }
#pragma unroll
    for (int off = 16; off; off >>= 1)
#pragma unroll
        for (int e = 0; e < E_NUM; e++)
            acc[e] += __shfl_xor_sync(0xffffffffu, acc[e], off);
    if (lane == 0) {
#pragma unroll
        for (int e = 0; e < E_NUM; e++) acc[e] += rb[e];
        int i0 = 0;
#pragma unroll
        for (int e = 1; e < E_NUM; e++) if (acc[e] > acc[i0]) i0 = e;
        int i1 = (i0 == 0) ? 1 : 0;
#pragma unroll
        for (int e = 0; e < E_NUM; e++)
            if (e != i0 && acc[e] > acc[i1]) i1 = e;
        float ex = expf(acc[i1] - acc[i0]);
        g_e01[2*gw] = i0;  g_e01[2*gw+1] = i1;
        g_p01[2*gw] = 1.f / (1.f + ex);
        g_p01[2*gw+1] = ex / (1.f + ex);
        atomicAdd(&g_counts[i0], 1);
        atomicAdd(&g_counts[i1], 1);
    }

    __threadfence();
    __syncthreads();
    if (tid == 0)
        s_flag = (atomicAdd(&g_block_done, 1) == (int)gridDim.x - 1);
    __syncthreads();
    if (!s_flag) return;
    __threadfence();

    if (tid == 0) {
        int off = 0;
        for (int e = 0; e < E_NUM; e++) {
            s_offs[e] = off;
            int nt = (g_counts[e] + TM - 1) / TM;
            for (int i = 0; i < nt; i++) g_tile_expert[off / TM + i] = e;
            off += nt * TM;
        }
        for (int i = off / TM; i < MAX_TILES; i++) g_tile_expert[i] = -1;
    }
    __syncthreads();

    int lc[E_NUM];
#pragma unroll
    for (int e = 0; e < E_NUM; e++) lc[e] = 0;
    for (int j = 0; j < 32; j++) {
        int t = j * 256 + tid;
        int e0 = g_e01[2*t], e1 = g_e01[2*t+1];
#pragma unroll
        for (int e = 0; e < E_NUM; e++) lc[e] += (e == e0) + (e == e1);
    }
#pragma unroll
    for (int e = 0; e < E_NUM; e++) s_cnt[e][tid] = lc[e];
    __syncthreads();

    {
        int wid = tid >> 5;
        int carry = 0;
        for (int seg = 0; seg < 8; seg++) {
            int v = s_cnt[wid][seg * 32 + lane];
            int inc = v;
#pragma unroll
            for (int o = 1; o < 32; o <<= 1) {
                int n = __shfl_up_sync(0xffffffffu, inc, o);
                if (lane >= o) inc += n;
            }
            s_excl[wid][seg * 32 + lane] = carry + inc - v;
            carry += __shfl_sync(0xffffffffu, inc, 31);
        }
    }
    __syncthreads();

#pragma unroll
    for (int e = 0; e < E_NUM; e++) lc[e] = 0;
    for (int j = 0; j < 32; j++) {
        int t = j * 256 + tid;
#pragma unroll
        for (int s = 0; s < 2; s++) {
            int e = g_e01[2*t + s];
            int pos = 0;
#pragma unroll
            for (int e2 = 0; e2 < E_NUM; e2++)
                if (e2 == e) { pos = lc[e2]; lc[e2]++; }
            int r = s_offs[e] + s_excl[e][tid] + pos;
            g_rowmap[r]  = t;
            g_rowprob[r] = g_p01[2*t + s];
            g_tokrow[2*t + s] = r;
        }
    }
}

/* ================= mma.sync GEMM core (128x128, KC=64, 3-stage) ============ */

__device__ __forceinline__ void load_stage(
    int c, int s, int nch, int tid,
    const __half* __restrict__ A, const __half* __restrict__ B,
    const unsigned* __restrict__ aoff, int col0, int K, uint32_t sb)
{
    if (c < nch) {
        uint32_t sbase = sb + (uint32_t)s * STG;
#pragma unroll
        for (int t = 0; t < 4; t++) {               /* A: 128 rows x 128B */
            int idx = tid + t * 256;
            int r = idx >> 3, seg = idx & 7;
            unsigned off = aoff[r] + (unsigned)c * KC + seg * 8;
            CP_ASYNC16(sbase + (uint32_t)r * PITCH + seg * 16, A + off);
        }
#pragma unroll
        for (int t = 0; t < 4; t++) {               /* B: 128 n-rows x 128B */
            int idx = tid + t * 256;
            int r = idx >> 3, seg = idx & 7;
            size_t off = (size_t)(col0 + r) * K + c * KC + seg * 8;
            CP_ASYNC16(sbase + PART + (uint32_t)r * PITCH + seg * 16, B + off);
        }
    }
    CP_COMMIT();
}

__device__ __forceinline__ void compute_stage(
    float acc[2][8][4], uint32_t sbase, int lane, int mbase, int nbase)
{
#pragma unroll
    for (int ks = 0; ks < 4; ks++) {
        uint32_t a[2][4], b[16];
        uint32_t arow = sbase + (uint32_t)(mbase + (lane & 15)) * PITCH
                        + ks * 32 + (lane >> 4) * 16;
#pragma unroll
        for (int mt = 0; mt < 2; mt++)
            ldsm_x4(a[mt], arow + mt * 16 * PITCH);
        uint32_t brow = sbase + PART
                        + (uint32_t)(nbase + ((lane >> 4) & 1) * 8 + (lane & 7)) * PITCH
                        + ks * 32 + ((lane >> 3) & 1) * 16;
#pragma unroll
        for (int p = 0; p < 4; p++)
            ldsm_x4(&b[p * 4], brow + p * 16 * PITCH);
#pragma unroll
        for (int mt = 0; mt < 2; mt++)
#pragma unroll
            for (int nt = 0; nt < 8; nt++)
                mma16816(acc[mt][nt], a[mt], &b[(nt >> 1) * 4 + (nt & 1) * 2]);
    }
}

__device__ __forceinline__ void gemm_mainloop(
    float acc[2][8][4],
    const __half* __restrict__ A, const __half* __restrict__ B,
    const unsigned* __restrict__ aoff, int col0, int K, int nch,
    uint32_t sb, int tid, int lane, int mbase, int nbase)
{
    load_stage(0, 0, nch, tid, A, B, aoff, col0, K, sb);
    load_stage(1, 1, nch, tid, A, B, aoff, col0, K, sb);
    int s = 0, sl = 2;
    for (int c = 0; c < nch; c++) {
        CP_WAIT1();
        __syncthreads();
        load_stage(c + 2, sl, nch, tid, A, B, aoff, col0, K, sb);
        compute_stage(acc, sb + (uint32_t)s * STG, lane, mbase, nbase);
        if (++s == NSTG) s = 0;
        if (++sl == NSTG) sl = 0;
    }
    __syncthreads();   /* all warps done with smem before epilogue reuses it */
}

__device__ __forceinline__ void stage_acc(float acc[2][8][4], float* sacc,
                                          int lane, int mbase, int nbase) {
    int groupID = lane >> 2, tig = lane & 3;
#pragma unroll
    for (int mt = 0; mt < 2; mt++)
#pragma unroll
        for (int nt = 0; nt < 8; nt++) {
            int r = mbase + mt * 16 + groupID;
            int cc = nbase + nt * 8 + tig * 2;
            sacc[r * 132 + cc]           = acc[mt][nt][0];
            sacc[r * 132 + cc + 1]       = acc[mt][nt][1];
            sacc[(r + 8) * 132 + cc]     = acc[mt][nt][2];
            sacc[(r + 8) * 132 + cc + 1] = acc[mt][nt][3];
        }
}

/* ------------- launch 4 (ncu target): GEMM1 -------------------------------- */
__global__ __launch_bounds__(256, 2)
void gemm1_mma(const float* __restrict__ b1) {
    int e = g_tile_expert[blockIdx.y];
    if (e < 0) return;
    extern __shared__ char smem[];
    uint32_t sb = smem_u32(smem);
    int tid = threadIdx.x, wid = tid >> 5, lane = tid & 31;
    int row0 = blockIdx.y * TM, col0 = blockIdx.x * TM;
    int mbase = (wid >> 1) * 32, nbase = (wid & 1) * 64;
    int* srows = (int*)(smem + SMEM_SROWS);
    unsigned* aoff = (unsigned*)(smem + SMEM_AOFF);

    if (tid < TM) {
        int rm = g_rowmap[row0 + tid];
        srows[tid] = rm;
        aoff[tid] = (unsigned)((rm < 0 ? 0 : rm) * H_DIM);
    }
    __syncthreads();

    float acc[2][8][4];
#pragma unroll
    for (int i = 0; i < 2; i++)
#pragma unroll
        for (int j = 0; j < 8; j++)
#pragma unroll
            for (int q = 0; q < 4; q++) acc[i][j][q] = 0.f;

    gemm_mainloop(acc, g_xh, g_w1 + (size_t)e * F_DIM * H_DIM,
                  aoff, col0, H_DIM, H_DIM / KC, sb, tid, lane, mbase, nbase);

    float* sacc = (float*)smem;
    stage_acc(acc, sacc, lane, mbase, nbase);
    __syncthreads();

    int row = tid >> 1, hc = (tid & 1) * 64;
    if (srows[row] >= 0) {
        const float* bp = b1 + (size_t)e * F_DIM + col0 + hc;
        __half* dh = g_h + (size_t)(row0 + row) * F_DIM + col0 + hc;
        const float* sp = sacc + row * 132 + hc;
        unsigned u[32];
#pragma unroll
        for (int j = 0; j < 32; j++) {
            float v0 = sp[2*j]   + bp[2*j];
            float v1 = sp[2*j+1] + bp[2*j+1];
            v0 = v0 > 0.f ? v0 : 0.f;
            v1 = v1 > 0.f ? v1 : 0.f;
            __half2 h2 = __floats2half2_rn(v0, v1);
            u[j] = *(unsigned*)&h2;
        }
#pragma unroll
        for (int q = 0; q < 8; q++)
            *(uint4*)(dh + q * 8) = make_uint4(u[4*q], u[4*q+1], u[4*q+2], u[4*q+3]);
    }
}

/* ------------- launch 5: GEMM2 (stores p*(acc+b2) to g_eout) --------------- */
__global__ __launch_bounds__(256, 2)
void gemm2_mma(const float* __restrict__ b2) {
    int e = g_tile_expert[blockIdx.y];
    if (e < 0) return;
    extern __shared__ char smem[];
    uint32_t sb = smem_u32(smem);
    int tid = threadIdx.x, wid = tid >> 5, lane = tid & 31;
    int row0 = blockIdx.y * TM, col0 = blockIdx.x * TM;
    int mbase = (wid >> 1) * 32, nbase = (wid & 1) * 64;
    int* srows = (int*)(smem + SMEM_SROWS);
    unsigned* aoff = (unsigned*)(smem + SMEM_AOFF);

    if (tid < TM) {
        srows[tid] = g_rowmap[row0 + tid];
        aoff[tid] = (unsigned)((row0 + tid) * F_DIM);
    }
    __syncthreads();

    float acc[2][8][4];
#pragma unroll
    for (int i = 0; i < 2; i++)
#pragma unroll
        for (int j = 0; j < 8; j++)
#pragma unroll
            for (int q = 0; q < 4; q++) acc[i][j][q] = 0.f;

    gemm_mainloop(acc, g_h, g_w2 + (size_t)e * H_DIM * F_DIM,
                  aoff, col0, F_DIM, F_DIM / KC, sb, tid, lane, mbase, nbase);

    float* sacc = (float*)smem;
    stage_acc(acc, sacc, lane, mbase, nbase);
    __syncthreads();

    int row = tid >> 1, hc = (tid & 1) * 64;
    int rm = srows[row];
    if (rm >= 0) {
        float p = g_rowprob[row0 + row];
        const float* bp = b2 + (size_t)e * H_DIM + col0 + hc;
        float* op = g_eout + (size_t)(row0 + row) * H_DIM + col0 + hc;
        const float* sp = sacc + row * 132 + hc;
#pragma unroll
        for (int q = 0; q < 16; q++) {
            float4 v;
            v.x = p * (sp[4*q]   + bp[4*q]);
            v.y = p * (sp[4*q+1] + bp[4*q+1]);
            v.z = p * (sp[4*q+2] + bp[4*q+2]);
            v.w = p * (sp[4*q+3] + bp[4*q+3]);
            *(float4*)(op + 4*q) = v;
        }
    }
}

/* ------------- launch 6: combine two expert rows per token ----------------- */
__global__ void combine_kernel(float* __restrict__ out) {
    int i = blockIdx.x * blockDim.x + threadIdx.x;
    int t = i >> 8, j = i & 255;
    int r0 = g_tokrow[2*t], r1 = g_tokrow[2*t+1];
    float4 a = *((const float4*)g_eout + (size_t)r0 * 256 + j);
    float4 b = *((const float4*)g_eout + (size_t)r1 * 256 + j);
    float4 v; v.x = a.x + b.x; v.y = a.y + b.y; v.z = a.z + b.z; v.w = a.w + b.w;
    *((float4*)out + (size_t)t * 256 + j) = v;
}

/* ================= launch ================= */
extern "C" void kernel_launch(void* const* d_in, const int* in_sizes, int n_in,
                              void* d_out, int out_size) {
    const float* x  = (const float*)d_in[0];
    const float* rw = (const float*)d_in[1];
    const float* rb = (const float*)d_in[2];
    const float* w1 = (const float*)d_in[3];
    const float* b1 = (const float*)d_in[4];
    const float* w2 = (const float*)d_in[5];
    const float* b2 = (const float*)d_in[6];
    float* out = (float*)d_out;

    cudaFuncSetAttribute(gemm1_mma, cudaFuncAttributeMaxDynamicSharedMemorySize, SMEM_TOTAL);
    cudaFuncSetAttribute(gemm2_mma, cudaFuncAttributeMaxDynamicSharedMemorySize, SMEM_TOTAL);

    /* 1 */ init_kernel<<<(MAX_ROWS + 255) / 256, 256>>>();
    /* 2 */ conv_w_all<<<dim3(64, 64, 2 * E_NUM), 128>>>(w1, w2);
    /* 3 */ router_kernel<<<T_TOK * 32 / 256, 256>>>(x, rw, rb);
    /* 4 */ gemm1_mma<<<dim3(F_DIM / TM, MAX_TILES), 256, SMEM_TOTAL>>>(b1);  /* ncu lands here */
    /* 5 */ gemm2_mma<<<dim3(H_DIM / TM, MAX_TILES), 256, SMEM_TOTAL>>>(b2);
    /* 6 */ combine_kernel<<<T_TOK * (H_DIM/4) / 256, 256>>>(out);
}

// round 14
// speedup vs baseline: 1.1514x; 1.1104x over previous
#include <cuda_runtime.h>
#include <cuda_fp16.h>
#include <math.h>
#include <stdint.h>

#define T_TOK 8192
#define H_DIM 1024
#define E_NUM 8
#define F_DIM 2048
#define TM 128
#define MAX_ROWS (2*T_TOK + E_NUM*TM)   /* 17408 */
#define MAX_TILES (MAX_ROWS/TM)         /* 136   */

#define KC    64            /* k-elements per chunk */
#define PITCH 144           /* 128B data + 16B pad (9 segs, coprime w/ 8) */
#define PART  18432         /* 128 rows * 144B */
#define STG   (2*PART)      /* A | B = 36864 */
#define NSTG  3
#define SMEM_SROWS (NSTG*STG)          /* 110592 */
#define SMEM_AOFF  (SMEM_SROWS + 512)
#define SMEM_TOTAL (SMEM_AOFF + 512)   /* 111616 -> 2 CTAs/SM */

/* ================= PTX helpers (family-common: sm_80+ only) ================= */
__device__ __forceinline__ uint32_t smem_u32(const void* p) {
    uint32_t a;
    asm("{ .reg .u64 t; cvta.to.shared.u64 t, %1; cvt.u32.u64 %0, t; }" : "=r"(a) : "l"(p));
    return a;
}
#define CP_ASYNC16(saddr, gptr) \
    asm volatile("cp.async.cg.shared.global [%0], [%1], 16;" :: "r"(saddr), "l"(gptr))
#define CP_COMMIT() asm volatile("cp.async.commit_group;" ::: "memory")
#define CP_WAIT1()  asm volatile("cp.async.wait_group 1;" ::: "memory")

__device__ __forceinline__ void ldsm_x4(uint32_t* r, uint32_t addr) {
    asm volatile("ldmatrix.sync.aligned.m8n8.x4.shared.b16 {%0,%1,%2,%3}, [%4];"
        : "=r"(r[0]), "=r"(r[1]), "=r"(r[2]), "=r"(r[3]) : "r"(addr));
}
__device__ __forceinline__ void mma16816(float* d, const uint32_t* a, const uint32_t* b) {
    asm volatile("mma.sync.aligned.m16n8k16.row.col.f32.f16.f16.f32 "
        "{%0,%1,%2,%3}, {%4,%5,%6,%7}, {%8,%9}, {%0,%1,%2,%3};"
        : "+f"(d[0]), "+f"(d[1]), "+f"(d[2]), "+f"(d[3])
        : "r"(a[0]), "r"(a[1]), "r"(a[2]), "r"(a[3]), "r"(b[0]), "r"(b[1]));
}

/* ================= scratch (device globals) ================= */
__device__ __half g_xh[(size_t)T_TOK * H_DIM];
__device__ __half g_w1[(size_t)E_NUM * F_DIM * H_DIM];   /* [e][n=F][k=H] */
__device__ __half g_w2[(size_t)E_NUM * H_DIM * F_DIM];   /* [e][n=H][k=F] */
__device__ __half g_h[(size_t)MAX_ROWS * F_DIM];         /* pad rows stay 0 */
__device__ float g_eout[(size_t)MAX_ROWS * H_DIM];
__device__ int   g_rowmap[MAX_ROWS];
__device__ float g_rowprob[MAX_ROWS];
__device__ int   g_tokrow[T_TOK * 2];
__device__ int   g_counts[E_NUM];
__device__ int   g_tile_expert[MAX_TILES];
__device__ int   g_e01[T_TOK*2];
__device__ float g_p01[T_TOK*2];
__device__ int   g_block_done;

/* ========== launch 1: tiny bookkeeping init ================================ */
__global__ void init_kernel() {
    int i = blockIdx.x * blockDim.x + threadIdx.x;
    if (i < MAX_ROWS) g_rowmap[i] = -1;
    if (i < E_NUM) g_counts[i] = 0;
    if (i == 0) g_block_done = 0;
}

/* ========== launch 2: weight transpose conversions (vectorized) ============ */
__device__ __forceinline__ void conv_w_body(const float* __restrict__ w,
                                            __half* __restrict__ dst,
                                            int K, int N, int e) {
    __shared__ float t[32][33];
    int n0 = blockIdx.x * 32;
    int k0 = blockIdx.y * 32;
    if (n0 >= N || k0 >= K) return;   /* block-uniform */
    int tid = threadIdx.x;            /* 128 threads */
    const float* src = w + (size_t)e * K * N;

    {
        int k = tid >> 3, n4 = (tid & 7) * 4;
#pragma unroll
        for (int p = 0; p < 2; p++) {
            float4 v = *(const float4*)(src + (size_t)(k0 + k + p*16) * N + n0 + n4);
            t[k + p*16][n4]   = v.x;  t[k + p*16][n4+1] = v.y;
            t[k + p*16][n4+2] = v.z;  t[k + p*16][n4+3] = v.w;
        }
    }
    __syncthreads();

    {
        int n = tid & 31, kseg = (tid >> 5) * 8;
        unsigned u[4];
#pragma unroll
        for (int q = 0; q < 4; q++) {
            __half2 h2 = __floats2half2_rn(t[kseg + 2*q][n], t[kseg + 2*q + 1][n]);
            u[q] = *(unsigned*)&h2;
        }
        *(uint4*)(dst + ((size_t)e * N + n0 + n) * K + k0 + kseg) =
            make_uint4(u[0], u[1], u[2], u[3]);
    }
}
__global__ void conv_w_all(const float* __restrict__ w1, const float* __restrict__ w2) {
    int z = blockIdx.z;
    if (z < E_NUM) conv_w_body(w1, g_w1, H_DIM, F_DIM, z);
    else           conv_w_body(w2, g_w2, F_DIM, H_DIM, z - E_NUM);
}

/* ========== launch 3: router (+x->fp16) + last-block scan + placement ====== */
__global__ void router_kernel(const float* __restrict__ x,
                              const float* __restrict__ rw,
                              const float* __restrict__ rb) {
    __shared__ int s_cnt[E_NUM][256];
    __shared__ int s_excl[E_NUM][256];
    __shared__ int s_offs[E_NUM];
    __shared__ int s_flag;

    int tid  = threadIdx.x;
    int gw   = (blockIdx.x * blockDim.x + tid) >> 5;
    int lane = tid & 31;
    const float* xp = x + (size_t)gw * H_DIM;
    __half* xhp = g_xh + (size_t)gw * H_DIM;
    float acc[E_NUM];
#pragma unroll
    for (int e = 0; e < E_NUM; e++) acc[e] = 0.f;
    for (int k = lane; k < H_DIM; k += 32) {
        float xv = xp[k];
        xhp[k] = __float2half_rn(xv);                 /* fused x conversion */
        const float4* w = (const float4*)(rw + (size_t)k * E_NUM);
        float4 w0 = w[0], w1v = w[1];
        acc[0] += xv * w0.x;  acc[1] += xv * w0.y;
        acc[2] += xv * w0.z;  acc[3] += xv * w0.w;
        acc[4] += xv * w1v.x; acc[5] += xv * w1v.y;
        acc[6] += xv * w1v.z; acc[7] += xv * w1v.w;
    }
#pragma unroll
    for (int off = 16; off; off >>= 1)
#pragma unroll
        for (int e = 0; e < E_NUM; e++)
            acc[e] += __shfl_xor_sync(0xffffffffu, acc[e], off);
    if (lane == 0) {
#pragma unroll
        for (int e = 0; e < E_NUM; e++) acc[e] += rb[e];
        int i0 = 0;
#pragma unroll
        for (int e = 1; e < E_NUM; e++) if (acc[e] > acc[i0]) i0 = e;
        int i1 = (i0 == 0) ? 1 : 0;
#pragma unroll
        for (int e = 0; e < E_NUM; e++)
            if (e != i0 && acc[e] > acc[i1]) i1 = e;
        float ex = expf(acc[i1] - acc[i0]);
        g_e01[2*gw] = i0;  g_e01[2*gw+1] = i1;
        g_p01[2*gw] = 1.f / (1.f + ex);
        g_p01[2*gw+1] = ex / (1.f + ex);
        atomicAdd(&g_counts[i0], 1);
        atomicAdd(&g_counts[i1], 1);
    }

    __threadfence();
    __syncthreads();
    if (tid == 0)
        s_flag = (atomicAdd(&g_block_done, 1) == (int)gridDim.x - 1);
    __syncthreads();
    if (!s_flag) return;
    __threadfence();

    if (tid == 0) {
        int off = 0;
        for (int e = 0; e < E_NUM; e++) {
            s_offs[e] = off;
            int nt = (g_counts[e] + TM - 1) / TM;
            for (int i = 0; i < nt; i++) g_tile_expert[off / TM + i] = e;
            off += nt * TM;
        }
        for (int i = off / TM; i < MAX_TILES; i++) g_tile_expert[i] = -1;
    }
    __syncthreads();

    int lc[E_NUM];
#pragma unroll
    for (int e = 0; e < E_NUM; e++) lc[e] = 0;
    for (int j = 0; j < 32; j++) {
        int t = j * 256 + tid;
        int e0 = g_e01[2*t], e1 = g_e01[2*t+1];
#pragma unroll
        for (int e = 0; e < E_NUM; e++) lc[e] += (e == e0) + (e == e1);
    }
#pragma unroll
    for (int e = 0; e < E_NUM; e++) s_cnt[e][tid] = lc[e];
    __syncthreads();

    {
        int wid = tid >> 5;
        int carry = 0;
        for (int seg = 0; seg < 8; seg++) {
            int v = s_cnt[wid][seg * 32 + lane];
            int inc = v;
#pragma unroll
            for (int o = 1; o < 32; o <<= 1) {
                int n = __shfl_up_sync(0xffffffffu, inc, o);
                if (lane >= o) inc += n;
            }
            s_excl[wid][seg * 32 + lane] = carry + inc - v;
            carry += __shfl_sync(0xffffffffu, inc, 31);
        }
    }
    __syncthreads();

#pragma unroll
    for (int e = 0; e < E_NUM; e++) lc[e] = 0;
    for (int j = 0; j < 32; j++) {
        int t = j * 256 + tid;
#pragma unroll
        for (int s = 0; s < 2; s++) {
            int e = g_e01[2*t + s];
            int pos = 0;
#pragma unroll
            for (int e2 = 0; e2 < E_NUM; e2++)
                if (e2 == e) { pos = lc[e2]; lc[e2]++; }
            int r = s_offs[e] + s_excl[e][tid] + pos;
            g_rowmap[r]  = t;
            g_rowprob[r] = g_p01[2*t + s];
            g_tokrow[2*t + s] = r;
        }
    }
}

/* ================= mma.sync GEMM core (128x128, KC=64, 3-stage) ============ */
/* One slice = 1/4 of a chunk's loads (A 32 rows + B 32 rows). Slices are     */
/* issued one per ks iteration inside the compute loop so cp.async issue      */
/* interleaves with HMMA instead of bursting at chunk start.                  */

__device__ __forceinline__ void load_slice(
    int c, int s, int slice, int nch, int tid,
    const __half* __restrict__ A, const __half* __restrict__ B,
    const unsigned* __restrict__ aoff, int col0, int K, uint32_t sb)
{
    if (c < nch) {
        uint32_t sbase = sb + (uint32_t)s * STG;
        int idx = tid + slice * 256;
        int r = idx >> 3, seg = idx & 7;
        {   /* A: 32 rows x 128B per slice */
            unsigned off = aoff[r] + (unsigned)c * KC + seg * 8;
            CP_ASYNC16(sbase + (uint32_t)r * PITCH + seg * 16, A + off);
        }
        {   /* B: 32 n-rows x 128B per slice */
            size_t off = (size_t)(col0 + r) * K + c * KC + seg * 8;
            CP_ASYNC16(sbase + PART + (uint32_t)r * PITCH + seg * 16, B + off);
        }
    }
}

__device__ __forceinline__ void gemm_mainloop(
    float acc[2][8][4],
    const __half* __restrict__ A, const __half* __restrict__ B,
    const unsigned* __restrict__ aoff, int col0, int K, int nch,
    uint32_t sb, int tid, int lane, int mbase, int nbase)
{
#pragma unroll
    for (int sl0 = 0; sl0 < 4; sl0++) load_slice(0, 0, sl0, nch, tid, A, B, aoff, col0, K, sb);
    CP_COMMIT();
#pragma unroll
    for (int sl0 = 0; sl0 < 4; sl0++) load_slice(1, 1, sl0, nch, tid, A, B, aoff, col0, K, sb);
    CP_COMMIT();

    int s = 0, sl = 2;
    for (int c = 0; c < nch; c++) {
        CP_WAIT1();
        __syncthreads();
        uint32_t sbase = sb + (uint32_t)s * STG;
#pragma unroll
        for (int ks = 0; ks < 4; ks++) {
            /* interleaved: one load slice for chunk c+2, then this ks's MMAs */
            load_slice(c + 2, sl, ks, nch, tid, A, B, aoff, col0, K, sb);

            uint32_t a[2][4], b[16];
            uint32_t arow = sbase + (uint32_t)(mbase + (lane & 15)) * PITCH
                            + ks * 32 + (lane >> 4) * 16;
#pragma unroll
            for (int mt = 0; mt < 2; mt++)
                ldsm_x4(a[mt], arow + mt * 16 * PITCH);
            uint32_t brow = sbase + PART
                            + (uint32_t)(nbase + ((lane >> 4) & 1) * 8 + (lane & 7)) * PITCH
                            + ks * 32 + ((lane >> 3) & 1) * 16;
#pragma unroll
            for (int p = 0; p < 4; p++)
                ldsm_x4(&b[p * 4], brow + p * 16 * PITCH);
#pragma unroll
            for (int mt = 0; mt < 2; mt++)
#pragma unroll
                for (int nt = 0; nt < 8; nt++)
                    mma16816(acc[mt][nt], a[mt], &b[(nt >> 1) * 4 + (nt & 1) * 2]);
        }
        CP_COMMIT();
        if (++s == NSTG) s = 0;
        if (++sl == NSTG) sl = 0;
    }
    __syncthreads();   /* all warps done with smem before epilogue reuses it */
}

__device__ __forceinline__ void stage_acc(float acc[2][8][4], float* sacc,
                                          int lane, int mbase, int nbase) {
    int groupID = lane >> 2, tig = lane & 3;
#pragma unroll
    for (int mt = 0; mt < 2; mt++)
#pragma unroll
        for (int nt = 0; nt < 8; nt++) {
            int r = mbase + mt * 16 + groupID;
            int cc = nbase + nt * 8 + tig * 2;
            sacc[r * 132 + cc]           = acc[mt][nt][0];
            sacc[r * 132 + cc + 1]       = acc[mt][nt][1];
            sacc[(r + 8) * 132 + cc]     = acc[mt][nt][2];
            sacc[(r + 8) * 132 + cc + 1] = acc[mt][nt][3];
        }
}

/* ------------- launch 4 (ncu target): GEMM1 -------------------------------- */
__global__ __launch_bounds__(256, 2)
void gemm1_mma(const float* __restrict__ b1) {
    int e = g_tile_expert[blockIdx.y];
    if (e < 0) return;
    extern __shared__ char smem[];
    uint32_t sb = smem_u32(smem);
    int tid = threadIdx.x, wid = tid >> 5, lane = tid & 31;
    int row0 = blockIdx.y * TM, col0 = blockIdx.x * TM;
    int mbase = (wid >> 1) * 32, nbase = (wid & 1) * 64;
    int* srows = (int*)(smem + SMEM_SROWS);
    unsigned* aoff = (unsigned*)(smem + SMEM_AOFF);

    if (tid < TM) {
        int rm = g_rowmap[row0 + tid];
        srows[tid] = rm;
        aoff[tid] = (unsigned)((rm < 0 ? 0 : rm) * H_DIM);
    }
    __syncthreads();

    float acc[2][8][4];
#pragma unroll
    for (int i = 0; i < 2; i++)
#pragma unroll
        for (int j = 0; j < 8; j++)
#pragma unroll
            for (int q = 0; q < 4; q++) acc[i][j][q] = 0.f;

    gemm_mainloop(acc, g_xh, g_w1 + (size_t)e * F_DIM * H_DIM,
                  aoff, col0, H_DIM, H_DIM / KC, sb, tid, lane, mbase, nbase);

    float* sacc = (float*)smem;
    stage_acc(acc, sacc, lane, mbase, nbase);
    __syncthreads();

    int row = tid >> 1, hc = (tid & 1) * 64;
    if (srows[row] >= 0) {
        const float* bp = b1 + (size_t)e * F_DIM + col0 + hc;
        __half* dh = g_h + (size_t)(row0 + row) * F_DIM + col0 + hc;
        const float* sp = sacc + row * 132 + hc;
        unsigned u[32];
#pragma unroll
        for (int j = 0; j < 32; j++) {
            float v0 = sp[2*j]   + bp[2*j];
            float v1 = sp[2*j+1] + bp[2*j+1];
            v0 = v0 > 0.f ? v0 : 0.f;
            v1 = v1 > 0.f ? v1 : 0.f;
            __half2 h2 = __floats2half2_rn(v0, v1);
            u[j] = *(unsigned*)&h2;
        }
#pragma unroll
        for (int q = 0; q < 8; q++)
            *(uint4*)(dh + q * 8) = make_uint4(u[4*q], u[4*q+1], u[4*q+2], u[4*q+3]);
    }
}

/* ------------- launch 5: GEMM2 (stores p*(acc+b2) to g_eout) --------------- */
__global__ __launch_bounds__(256, 2)
void gemm2_mma(const float* __restrict__ b2) {
    int e = g_tile_expert[blockIdx.y];
    if (e < 0) return;
    extern __shared__ char smem[];
    uint32_t sb = smem_u32(smem);
    int tid = threadIdx.x, wid = tid >> 5, lane = tid & 31;
    int row0 = blockIdx.y * TM, col0 = blockIdx.x * TM;
    int mbase = (wid >> 1) * 32, nbase = (wid & 1) * 64;
    int* srows = (int*)(smem + SMEM_SROWS);
    unsigned* aoff = (unsigned*)(smem + SMEM_AOFF);

    if (tid < TM) {
        srows[tid] = g_rowmap[row0 + tid];
        aoff[tid] = (unsigned)((row0 + tid) * F_DIM);
    }
    __syncthreads();

    float acc[2][8][4];
#pragma unroll
    for (int i = 0; i < 2; i++)
#pragma unroll
        for (int j = 0; j < 8; j++)
#pragma unroll
            for (int q = 0; q < 4; q++) acc[i][j][q] = 0.f;

    gemm_mainloop(acc, g_h, g_w2 + (size_t)e * H_DIM * F_DIM,
                  aoff, col0, F_DIM, F_DIM / KC, sb, tid, lane, mbase, nbase);

    float* sacc = (float*)smem;
    stage_acc(acc, sacc, lane, mbase, nbase);
    __syncthreads();

    int row = tid >> 1, hc = (tid & 1) * 64;
    int rm = srows[row];
    if (rm >= 0) {
        float p = g_rowprob[row0 + row];
        const float* bp = b2 + (size_t)e * H_DIM + col0 + hc;
        float* op = g_eout + (size_t)(row0 + row) * H_DIM + col0 + hc;
        const float* sp = sacc + row * 132 + hc;
#pragma unroll
        for (int q = 0; q < 16; q++) {
            float4 v;
            v.x = p * (sp[4*q]   + bp[4*q]);
            v.y = p * (sp[4*q+1] + bp[4*q+1]);
            v.z = p * (sp[4*q+2] + bp[4*q+2]);
            v.w = p * (sp[4*q+3] + bp[4*q+3]);
            *(float4*)(op + 4*q) = v;
        }
    }
}

/* ------------- launch 6: combine two expert rows per token ----------------- */
__global__ void combine_kernel(float* __restrict__ out) {
    int i = blockIdx.x * blockDim.x + threadIdx.x;
    int t = i >> 8, j = i & 255;
    int r0 = g_tokrow[2*t], r1 = g_tokrow[2*t+1];
    float4 a = *((const float4*)g_eout + (size_t)r0 * 256 + j);
    float4 b = *((const float4*)g_eout + (size_t)r1 * 256 + j);
    float4 v; v.x = a.x + b.x; v.y = a.y + b.y; v.z = a.z + b.z; v.w = a.w + b.w;
    *((float4*)out + (size_t)t * 256 + j) = v;
}

/* ================= launch ================= */
extern "C" void kernel_launch(void* const* d_in, const int* in_sizes, int n_in,
                              void* d_out, int out_size) {
    const float* x  = (const float*)d_in[0];
    const float* rw = (const float*)d_in[1];
    const float* rb = (const float*)d_in[2];
    const float* w1 = (const float*)d_in[3];
    const float* b1 = (const float*)d_in[4];
    const float* w2 = (const float*)d_in[5];
    const float* b2 = (const float*)d_in[6];
    float* out = (float*)d_out;

    cudaFuncSetAttribute(gemm1_mma, cudaFuncAttributeMaxDynamicSharedMemorySize, SMEM_TOTAL);
    cudaFuncSetAttribute(gemm2_mma, cudaFuncAttributeMaxDynamicSharedMemorySize, SMEM_TOTAL);

    /* 1 */ init_kernel<<<(MAX_ROWS + 255) / 256, 256>>>();
    /* 2 */ conv_w_all<<<dim3(64, 64, 2 * E_NUM), 128>>>(w1, w2);
    /* 3 */ router_kernel<<<T_TOK * 32 / 256, 256>>>(x, rw, rb);
    /* 4 */ gemm1_mma<<<dim3(F_DIM / TM, MAX_TILES), 256, SMEM_TOTAL>>>(b1);  /* ncu lands here */
    /* 5 */ gemm2_mma<<<dim3(H_DIM / TM, MAX_TILES), 256, SMEM_TOTAL>>>(b2);
    /* 6 */ combine_kernel<<<T_TOK * (H_DIM/4) / 256, 256>>>(out);
}